// round 6
// baseline (speedup 1.0000x reference)
#include <cuda_runtime.h>
#include <cstdint>

#define T_STEPS 256
#define BATCH   128
#define IN_DIM  512
#define HID     512
#define COMB    1024
#define NCOL    2048
#define BH      (BATCH*HID)            // 65536
#define TBH     (T_STEPS*BATCH*HID)    // 16777216
#define NB      128
#define WPITCH  516                    // floats per ws row
#define CHUNKF  8192                   // floats per h chunk buffer (128b x 64k)

typedef unsigned long long u64;

// ------------------------- device scratch
__device__ float g_pre[(size_t)T_STEPS * NCOL * BATCH];  // [t][col][b]
__device__ float g_cosv[BATCH * NCOL];                   // [b][col]
__device__ float g_h[BH];                                // [b][k]
__device__ u64   g_flag[NB];                             // monotonic rounds

// ------------------------- f32x2 packed helpers (sm_100+)
__device__ __forceinline__ u64 ffma2(u64 a, u64 b, u64 c) {
    u64 d; asm("fma.rn.f32x2 %0,%1,%2,%3;" : "=l"(d) : "l"(a), "l"(b), "l"(c));
    return d;
}
__device__ __forceinline__ u64 fadd2(u64 a, u64 b) {
    u64 d; asm("add.rn.f32x2 %0,%1,%2;" : "=l"(d) : "l"(a), "l"(b));
    return d;
}
__device__ __forceinline__ void unpack2(u64 v, float& lo, float& hi) {
    asm("mov.b64 {%0,%1},%2;" : "=f"(lo), "=f"(hi) : "l"(v));
}
__device__ __forceinline__ void cpasync16(uint32_t dst, const void* src) {
    asm volatile("cp.async.cg.shared.global [%0], [%1], 16;" :: "r"(dst), "l"(src));
}

// ===========================================================================
// Kernel 1: input projection GEMM (unchanged from passing R4 kernel).
// PRE[t][col][b] = x@Wg^T + bg + theta_g.
// ===========================================================================
__global__ void __launch_bounds__(256) pre_gemm(
    const float* __restrict__ x,
    const float* __restrict__ Wf, const float* __restrict__ bf, const float* __restrict__ thf,
    const float* __restrict__ Wi, const float* __restrict__ bi, const float* __restrict__ thi,
    const float* __restrict__ Wu, const float* __restrict__ bu, const float* __restrict__ thu,
    const float* __restrict__ Wo, const float* __restrict__ bo, const float* __restrict__ tho)
{
    __shared__ float As[8 * 132];
    __shared__ float Bs[8 * 132];

    const int tid = threadIdx.x;
    const int bx = blockIdx.x;
    const int by = blockIdx.y;
    const int m0 = by * 128;
    const int c0 = bx * 128;
    const int gate = c0 >> 9;
    const int nb = c0 & 511;
    const float* Wg = gate == 0 ? Wf : gate == 1 ? Wi : gate == 2 ? Wu : Wo;
    const float* bg = gate == 0 ? bf : gate == 1 ? bi : gate == 2 ? bu : bo;
    const float* tg = gate == 0 ? thf : gate == 1 ? thi : gate == 2 ? thu : tho;

    const int tx = tid & 15;
    const int ty = tid >> 4;
    const int lr = tid >> 1;
    const int lq = (tid & 1) * 4;
    const float* Aptr = x  + (size_t)(m0 + lr) * IN_DIM + lq;
    const float* Bptr = Wg + (size_t)(nb + lr) * COMB   + lq;

    u64 acc[8][4];
#pragma unroll
    for (int r = 0; r < 8; r++)
#pragma unroll
        for (int cp = 0; cp < 4; cp++) acc[r][cp] = 0ULL;

    float4 a4 = *(const float4*)Aptr;
    float4 b4 = *(const float4*)Bptr;

    for (int ck = 0; ck < 64; ck++) {
        As[(lq+0)*132+lr] = a4.x; As[(lq+1)*132+lr] = a4.y;
        As[(lq+2)*132+lr] = a4.z; As[(lq+3)*132+lr] = a4.w;
        Bs[(lq+0)*132+lr] = b4.x; Bs[(lq+1)*132+lr] = b4.y;
        Bs[(lq+2)*132+lr] = b4.z; Bs[(lq+3)*132+lr] = b4.w;
        __syncthreads();
        if (ck < 63) {
            a4 = *(const float4*)(Aptr + (ck + 1) * 8);
            b4 = *(const float4*)(Bptr + (ck + 1) * 8);
        }
#pragma unroll
        for (int kk = 0; kk < 8; kk++) {
            float4 av0 = *(float4*)&As[kk*132 + 8*ty];
            float4 av1 = *(float4*)&As[kk*132 + 8*ty + 4];
            ulonglong2 bl0 = *(ulonglong2*)&Bs[kk*132 + 8*tx];
            ulonglong2 bl1 = *(ulonglong2*)&Bs[kk*132 + 8*tx + 4];
            float a[8] = {av0.x, av0.y, av0.z, av0.w, av1.x, av1.y, av1.z, av1.w};
#pragma unroll
            for (int r = 0; r < 8; r++) {
                u64 ap; asm("mov.b64 %0,{%1,%1};" : "=l"(ap) : "f"(a[r]));
                acc[r][0] = ffma2(ap, bl0.x, acc[r][0]);
                acc[r][1] = ffma2(ap, bl0.y, acc[r][1]);
                acc[r][2] = ffma2(ap, bl1.x, acc[r][2]);
                acc[r][3] = ffma2(ap, bl1.y, acc[r][3]);
            }
        }
        __syncthreads();
    }

    float bt[8];
#pragma unroll
    for (int i = 0; i < 8; i++) bt[i] = bg[nb + 8*tx + i] + tg[nb + 8*tx + i];
#pragma unroll
    for (int cc = 0; cc < 8; cc++) {
        float o[8];
#pragma unroll
        for (int r = 0; r < 8; r++) {
            float lo, hi; unpack2(acc[r][cc >> 1], lo, hi);
            o[r] = ((cc & 1) ? hi : lo) + bt[cc];
        }
        size_t base = ((size_t)by * NCOL + c0 + 8*tx + cc) * BATCH + 8*ty;
        *(float4*)&g_pre[base]     = make_float4(o[0], o[1], o[2], o[3]);
        *(float4*)&g_pre[base + 4] = make_float4(o[4], o[5], o[6], o[7]);
    }
}

// ------------------------- flag-array grid barrier (graph-replay safe)
__device__ __forceinline__ void gridbar(u64 rnd) {
    __syncthreads();
    if (threadIdx.x == 0) {
        asm volatile("st.release.gpu.global.u64 [%0], %1;"
                     :: "l"(&g_flag[blockIdx.x]), "l"(rnd) : "memory");
    }
    if (threadIdx.x < NB) {
        u64 v;
        do {
            asm volatile("ld.acquire.gpu.global.u64 %0, [%1];"
                         : "=l"(v) : "l"(&g_flag[threadIdx.x]) : "memory");
        } while (v < rnd);
    }
    __syncthreads();
}

// ===========================================================================
// Kernel 2: persistent recurrent kernel.  128 CTAs x 512 thr (16 warps/SM).
//  Phase A: CTA j computes cols [16j,16j+16) of V = PRE + h@Wh^T for all
//   128 batches.  Thread tile: 2 cols x 4 batches x K/2 (K-split across
//   thread halves, combined via smem).  h staged by cp.async.cg into 3
//   rotating smem buffers (64-k x 128-b chunks), XOR-swizzled.
//  Phase B: batch j: two-level cumprod scan per gate, activations, cell.
// ===========================================================================
__global__ void __launch_bounds__(512) qlstm_recur(
    const float* __restrict__ Wf, const float* __restrict__ Wi,
    const float* __restrict__ Wu, const float* __restrict__ Wo,
    float* __restrict__ out, int wstate)
{
    extern __shared__ float sm[];
    float* ws   = sm;                          // 8256 floats
    float* hs   = sm + 8256;                   // 3*8192 = 24576
    float* gsm  = sm + 8256 + 24576;           // 2048
    float* csm  = gsm + 2048;                  // 512
    float* wtot = csm + 512;                   // 16

    const int tid = threadIdx.x;
    const int j   = blockIdx.x;

    const int kh  = tid >> 8;                  // K half (0/1)
    const int r   = tid & 255;
    const int cp  = r & 7;                     // col pair
    const int bq  = r >> 3;                    // 0..31
    const int cA0 = 2 * cp, cA1 = 2 * cp + 1;
    const int col0 = j * 16 + cA0;
    const int gA   = col0 >> 9;
    const int n0   = (j * 16) & 511;
    const float* WgB = gA == 0 ? Wf : gA == 1 ? Wi : gA == 2 ? Wu : Wo;
    const int swc0 = cA0 >> 3;
    const int swc1 = cA1 >> 3;
    const int swb  = bq & 7;

    uint32_t hs_u32;
    { unsigned long long p = __cvta_generic_to_shared(hs); hs_u32 = (uint32_t)p; }

    u64 rnd;
    asm volatile("ld.acquire.gpu.global.u64 %0, [%1];"
                 : "=l"(rnd) : "l"(&g_flag[j]) : "memory");

    // cache recurrent weight slice (hidden half), XOR-swizzled quads
    for (int e = tid; e < 16 * 512; e += 512) {
        int cc = e >> 9, k = e & 511;
        int k4 = k >> 2, kr = k & 3;
        int sq = k4 ^ (cc >> 3);
        ws[cc * WPITCH + sq * 4 + kr] = WgB[(size_t)(n0 + cc) * COMB + 512 + k];
    }
    g_h[j * HID + tid] = 0.f;
    csm[tid & 511] = 0.f;   // 512 threads cover 512 exactly
    rnd++; gridbar(rnd);

    for (int t = 0; t < T_STEPS; t++) {
        // PRE loads (half0 only; consumed at epilogue, long slack)
        float4 pre0, pre1;
        if (kh == 0) {
            size_t pb = ((size_t)t * NCOL + col0) * BATCH + bq * 4;
            pre0 = __ldcg((const float4*)(g_pre + pb));
            pre1 = __ldcg((const float4*)(g_pre + pb + BATCH));
        }

        u64 acc[2][4];
#pragma unroll
        for (int c = 0; c < 2; c++)
#pragma unroll
            for (int i = 0; i < 4; i++) acc[c][i] = 0ULL;

        // prologue: stage chunk 0 into buf 0
        {
#pragma unroll
            for (int it = 0; it < 4; it++) {
                int e = it * 512 + tid;
                int bb = e >> 4, kq = e & 15;
                uint32_t dst = hs_u32 + (uint32_t)((bb * 64 + ((kq ^ ((bb >> 2) & 7)) << 2)) * 4);
                cpasync16(dst, g_h + bb * HID + kq * 4);
            }
            asm volatile("cp.async.commit_group;");
        }

#pragma unroll
        for (int ci = 0; ci < 8; ci++) {
            if (ci < 7) {
                int buf = (ci + 1) % 3;
#pragma unroll
                for (int it = 0; it < 4; it++) {
                    int e = it * 512 + tid;
                    int bb = e >> 4, kq = e & 15;
                    uint32_t dst = hs_u32 +
                        (uint32_t)((buf * CHUNKF + bb * 64 + ((kq ^ ((bb >> 2) & 7)) << 2)) * 4);
                    cpasync16(dst, g_h + bb * HID + (ci + 1) * 64 + kq * 4);
                }
                asm volatile("cp.async.commit_group;");
                asm volatile("cp.async.wait_group 1;");
            } else {
                asm volatile("cp.async.wait_group 0;");
            }
            __syncthreads();

            const float* hb  = hs + (ci % 3) * CHUNKF;
            const float* w0r = ws + cA0 * WPITCH;
            const float* w1r = ws + cA1 * WPITCH;
#pragma unroll
            for (int kq8 = 0; kq8 < 8; kq8++) {
                int kq  = kh * 8 + kq8;
                int k4a = ci * 16 + kq;
                ulonglong2 w0 = *(const ulonglong2*)(w0r + ((k4a ^ swc0) << 2));
                ulonglong2 w1 = *(const ulonglong2*)(w1r + ((k4a ^ swc1) << 2));
#pragma unroll
                for (int i = 0; i < 4; i++) {
                    int b = bq * 4 + i;
                    ulonglong2 hv = *(const ulonglong2*)(hb + b * 64 + ((kq ^ swb) << 2));
                    acc[0][i] = ffma2(hv.x, w0.x, acc[0][i]);
                    acc[0][i] = ffma2(hv.y, w0.y, acc[0][i]);
                    acc[1][i] = ffma2(hv.x, w1.x, acc[1][i]);
                    acc[1][i] = ffma2(hv.y, w1.y, acc[1][i]);
                }
            }
        }

        // combine K halves through smem (red area aliases buf 0)
        u64* red = (u64*)hs;
        if (kh == 1) {
#pragma unroll
            for (int c = 0; c < 2; c++)
#pragma unroll
                for (int i = 0; i < 4; i++) red[r * 8 + c * 4 + i] = acc[c][i];
        }
        __syncthreads();
        if (kh == 0) {
            float p0[4] = {pre0.x, pre0.y, pre0.z, pre0.w};
            float p1[4] = {pre1.x, pre1.y, pre1.z, pre1.w};
#pragma unroll
            for (int i = 0; i < 4; i++) {
                int b = bq * 4 + i;
                u64 s0 = fadd2(acc[0][i], red[r * 8 + i]);
                u64 s1 = fadd2(acc[1][i], red[r * 8 + 4 + i]);
                float lo, hi, v0, v1;
                unpack2(s0, lo, hi); v0 = lo + hi + p0[i];
                unpack2(s1, lo, hi); v1 = lo + hi + p1[i];
                *(float2*)&g_cosv[b * NCOL + col0] = make_float2(__cosf(v0), __cosf(v1));
            }
        }
        rnd++; gridbar(rnd);

        // ---------------- phase B: scan + activations + cell (batch = j) ---
        {
            int gate = tid >> 7;
            int lg   = tid & 127;
            int lane = tid & 31;
            int wg   = (tid >> 5) & 3;
            const float* src = g_cosv + j * NCOL + gate * HID + lg * 4;
            float4 a = __ldcg((const float4*)src);
            float xv[4] = {a.x, a.y, a.z, a.w};
            float p = xv[0] * xv[1] * xv[2] * xv[3];
            float inc = p;
#pragma unroll
            for (int off = 1; off < 32; off <<= 1) {
                float y = __shfl_up_sync(0xffffffffu, inc, off);
                if (lane >= off) inc *= y;
            }
            float excl = __shfl_up_sync(0xffffffffu, inc, 1);
            if (lane == 0) excl = 1.f;
            if (lane == 31) wtot[gate * 4 + wg] = inc;
            __syncthreads();
#pragma unroll
            for (int w = 0; w < 3; w++)
                if (wg > w) excl *= wtot[gate * 4 + w];
            float run = excl;
#pragma unroll
            for (int i = 0; i < 4; i++) {
                run *= xv[i];
                float act = (gate == 2) ? tanhf(run)
                                        : 1.f / (1.f + __expf(-run));
                gsm[gate * HID + lg * 4 + i] = act;
            }
        }
        __syncthreads();
        {
            int n = tid;
            float f  = gsm[n];
            float ii = gsm[HID + n];
            float gg = gsm[2 * HID + n];
            float o  = gsm[3 * HID + n];
            float cc = f * csm[n] + ii * gg;
            csm[n] = cc;
            float h = o * tanhf(cc);
            g_h[j * HID + n] = h;
            out[(size_t)t * BH + j * HID + n] = h;
            if (wstate && t == T_STEPS - 1) {
                out[(size_t)TBH + j * HID + n] = h;
                out[(size_t)TBH + BH + j * HID + n] = cc;
            }
        }
        rnd++; gridbar(rnd);
    }
}

#define RECUR_SMEM ((8256 + 24576 + 2048 + 512 + 16) * 4)

extern "C" void kernel_launch(void* const* d_in, const int* in_sizes, int n_in,
                              void* d_out, int out_size) {
    const float* x   = (const float*)d_in[0];
    const float* Wf  = (const float*)d_in[1];
    const float* bf  = (const float*)d_in[2];
    const float* thf = (const float*)d_in[3];
    const float* Wi  = (const float*)d_in[4];
    const float* bi  = (const float*)d_in[5];
    const float* thi = (const float*)d_in[6];
    const float* Wu  = (const float*)d_in[7];
    const float* bu  = (const float*)d_in[8];
    const float* thu = (const float*)d_in[9];
    const float* Wo  = (const float*)d_in[10];
    const float* bo  = (const float*)d_in[11];
    const float* tho = (const float*)d_in[12];
    float* out = (float*)d_out;
    int wstate = (out_size >= TBH + 2 * BH) ? 1 : 0;

    pre_gemm<<<dim3(16, 256), 256>>>(x, Wf, bf, thf, Wi, bi, thi,
                                     Wu, bu, thu, Wo, bo, tho);

    cudaFuncSetAttribute(qlstm_recur,
                         cudaFuncAttributeMaxDynamicSharedMemorySize, RECUR_SMEM);
    qlstm_recur<<<NB, 512, RECUR_SMEM>>>(Wf, Wi, Wu, Wo, out, wstate);
}

// round 7
// speedup vs baseline: 1.0072x; 1.0072x over previous
#include <cuda_runtime.h>
#include <cstdint>

#define T_STEPS 256
#define BATCH   128
#define IN_DIM  512
#define HID     512
#define COMB    1024
#define NCOL    2048
#define BH      (BATCH*HID)            // 65536
#define TBH     (T_STEPS*BATCH*HID)    // 16777216
#define NB      128
#define WPITCH  516                    // floats per ws row
#define CHUNKF  8192                   // floats per h chunk buffer (128b x 64k)

typedef unsigned long long u64;

// ------------------------- device scratch
__device__ float g_pre[(size_t)T_STEPS * NCOL * BATCH];  // [t][col][b]
__device__ float g_cosv[BATCH * NCOL];                   // [b][col]
__device__ float g_h[BH];                                // [b][k]
__device__ u64   g_flag[NB];                             // monotonic rounds

// ------------------------- f32x2 packed helpers (sm_100+)
__device__ __forceinline__ u64 ffma2(u64 a, u64 b, u64 c) {
    u64 d; asm("fma.rn.f32x2 %0,%1,%2,%3;" : "=l"(d) : "l"(a), "l"(b), "l"(c));
    return d;
}
__device__ __forceinline__ u64 fadd2(u64 a, u64 b) {
    u64 d; asm("add.rn.f32x2 %0,%1,%2;" : "=l"(d) : "l"(a), "l"(b));
    return d;
}
__device__ __forceinline__ void unpack2(u64 v, float& lo, float& hi) {
    asm("mov.b64 {%0,%1},%2;" : "=f"(lo), "=f"(hi) : "l"(v));
}
__device__ __forceinline__ void cpasync16(uint32_t dst, const void* src) {
    asm volatile("cp.async.cg.shared.global [%0], [%1], 16;" :: "r"(dst), "l"(src));
}

// ===========================================================================
// Kernel 1: input projection GEMM (unchanged from passing R4 kernel).
// PRE[t][col][b] = x@Wg^T + bg + theta_g.
// ===========================================================================
__global__ void __launch_bounds__(256) pre_gemm(
    const float* __restrict__ x,
    const float* __restrict__ Wf, const float* __restrict__ bf, const float* __restrict__ thf,
    const float* __restrict__ Wi, const float* __restrict__ bi, const float* __restrict__ thi,
    const float* __restrict__ Wu, const float* __restrict__ bu, const float* __restrict__ thu,
    const float* __restrict__ Wo, const float* __restrict__ bo, const float* __restrict__ tho)
{
    __shared__ float As[8 * 132];
    __shared__ float Bs[8 * 132];

    const int tid = threadIdx.x;
    const int bx = blockIdx.x;
    const int by = blockIdx.y;
    const int m0 = by * 128;
    const int c0 = bx * 128;
    const int gate = c0 >> 9;
    const int nb = c0 & 511;
    const float* Wg = gate == 0 ? Wf : gate == 1 ? Wi : gate == 2 ? Wu : Wo;
    const float* bg = gate == 0 ? bf : gate == 1 ? bi : gate == 2 ? bu : bo;
    const float* tg = gate == 0 ? thf : gate == 1 ? thi : gate == 2 ? thu : tho;

    const int tx = tid & 15;
    const int ty = tid >> 4;
    const int lr = tid >> 1;
    const int lq = (tid & 1) * 4;
    const float* Aptr = x  + (size_t)(m0 + lr) * IN_DIM + lq;
    const float* Bptr = Wg + (size_t)(nb + lr) * COMB   + lq;

    u64 acc[8][4];
#pragma unroll
    for (int r = 0; r < 8; r++)
#pragma unroll
        for (int cp = 0; cp < 4; cp++) acc[r][cp] = 0ULL;

    float4 a4 = *(const float4*)Aptr;
    float4 b4 = *(const float4*)Bptr;

    for (int ck = 0; ck < 64; ck++) {
        As[(lq+0)*132+lr] = a4.x; As[(lq+1)*132+lr] = a4.y;
        As[(lq+2)*132+lr] = a4.z; As[(lq+3)*132+lr] = a4.w;
        Bs[(lq+0)*132+lr] = b4.x; Bs[(lq+1)*132+lr] = b4.y;
        Bs[(lq+2)*132+lr] = b4.z; Bs[(lq+3)*132+lr] = b4.w;
        __syncthreads();
        if (ck < 63) {
            a4 = *(const float4*)(Aptr + (ck + 1) * 8);
            b4 = *(const float4*)(Bptr + (ck + 1) * 8);
        }
#pragma unroll
        for (int kk = 0; kk < 8; kk++) {
            float4 av0 = *(float4*)&As[kk*132 + 8*ty];
            float4 av1 = *(float4*)&As[kk*132 + 8*ty + 4];
            ulonglong2 bl0 = *(ulonglong2*)&Bs[kk*132 + 8*tx];
            ulonglong2 bl1 = *(ulonglong2*)&Bs[kk*132 + 8*tx + 4];
            float a[8] = {av0.x, av0.y, av0.z, av0.w, av1.x, av1.y, av1.z, av1.w};
#pragma unroll
            for (int r = 0; r < 8; r++) {
                u64 ap; asm("mov.b64 %0,{%1,%1};" : "=l"(ap) : "f"(a[r]));
                acc[r][0] = ffma2(ap, bl0.x, acc[r][0]);
                acc[r][1] = ffma2(ap, bl0.y, acc[r][1]);
                acc[r][2] = ffma2(ap, bl1.x, acc[r][2]);
                acc[r][3] = ffma2(ap, bl1.y, acc[r][3]);
            }
        }
        __syncthreads();
    }

    float bt[8];
#pragma unroll
    for (int i = 0; i < 8; i++) bt[i] = bg[nb + 8*tx + i] + tg[nb + 8*tx + i];
#pragma unroll
    for (int cc = 0; cc < 8; cc++) {
        float o[8];
#pragma unroll
        for (int r = 0; r < 8; r++) {
            float lo, hi; unpack2(acc[r][cc >> 1], lo, hi);
            o[r] = ((cc & 1) ? hi : lo) + bt[cc];
        }
        size_t base = ((size_t)by * NCOL + c0 + 8*tx + cc) * BATCH + 8*ty;
        *(float4*)&g_pre[base]     = make_float4(o[0], o[1], o[2], o[3]);
        *(float4*)&g_pre[base + 4] = make_float4(o[4], o[5], o[6], o[7]);
    }
}

// ------------------------- flag-array grid barrier (graph-replay safe)
__device__ __forceinline__ void gridbar(u64 rnd) {
    __syncthreads();
    if (threadIdx.x == 0) {
        asm volatile("st.release.gpu.global.u64 [%0], %1;"
                     :: "l"(&g_flag[blockIdx.x]), "l"(rnd) : "memory");
    }
    if (threadIdx.x < NB) {
        u64 v;
        do {
            asm volatile("ld.acquire.gpu.global.u64 %0, [%1];"
                         : "=l"(v) : "l"(&g_flag[threadIdx.x]) : "memory");
        } while (v < rnd);
    }
    __syncthreads();
}

// ===========================================================================
// Kernel 2: persistent recurrent kernel.  128 CTAs x 512 thr (16 warps/SM).
//  Phase A: CTA j computes cols [16j,16j+16) of V = PRE + h@Wh^T for all
//   128 batches.  Thread tile: 2 cols x 4 batches x K/2 (K-split across
//   thread halves, combined via smem).  h staged by cp.async.cg into 3
//   rotating smem buffers (64-k x 128-b chunks), XOR-swizzled.
//  Phase B: batch j: two-level cumprod scan per gate, activations, cell.
// ===========================================================================
__global__ void __launch_bounds__(512) qlstm_recur(
    const float* __restrict__ Wf, const float* __restrict__ Wi,
    const float* __restrict__ Wu, const float* __restrict__ Wo,
    float* __restrict__ out, int wstate)
{
    extern __shared__ float sm[];
    float* ws   = sm;                          // 8256 floats
    float* hs   = sm + 8256;                   // 3*8192 = 24576
    float* gsm  = sm + 8256 + 24576;           // 2048
    float* csm  = gsm + 2048;                  // 512
    float* wtot = csm + 512;                   // 16

    const int tid = threadIdx.x;
    const int j   = blockIdx.x;

    const int kh  = tid >> 8;                  // K half (0/1)
    const int r   = tid & 255;
    const int cp  = r & 7;                     // col pair
    const int bq  = r >> 3;                    // 0..31
    const int cA0 = 2 * cp, cA1 = 2 * cp + 1;
    const int col0 = j * 16 + cA0;
    const int gA   = col0 >> 9;
    const int n0   = (j * 16) & 511;
    const float* WgB = gA == 0 ? Wf : gA == 1 ? Wi : gA == 2 ? Wu : Wo;
    const int swc0 = cA0 >> 3;
    const int swc1 = cA1 >> 3;
    const int swb  = bq & 7;

    uint32_t hs_u32;
    { unsigned long long p = __cvta_generic_to_shared(hs); hs_u32 = (uint32_t)p; }

    u64 rnd;
    asm volatile("ld.acquire.gpu.global.u64 %0, [%1];"
                 : "=l"(rnd) : "l"(&g_flag[j]) : "memory");

    // cache recurrent weight slice (hidden half), XOR-swizzled quads
    for (int e = tid; e < 16 * 512; e += 512) {
        int cc = e >> 9, k = e & 511;
        int k4 = k >> 2, kr = k & 3;
        int sq = k4 ^ (cc >> 3);
        ws[cc * WPITCH + sq * 4 + kr] = WgB[(size_t)(n0 + cc) * COMB + 512 + k];
    }
    g_h[j * HID + tid] = 0.f;
    csm[tid & 511] = 0.f;   // 512 threads cover 512 exactly
    rnd++; gridbar(rnd);

    for (int t = 0; t < T_STEPS; t++) {
        // PRE loads (half0 only; consumed at epilogue, long slack)
        float4 pre0, pre1;
        if (kh == 0) {
            size_t pb = ((size_t)t * NCOL + col0) * BATCH + bq * 4;
            pre0 = __ldcg((const float4*)(g_pre + pb));
            pre1 = __ldcg((const float4*)(g_pre + pb + BATCH));
        }

        u64 acc[2][4];
#pragma unroll
        for (int c = 0; c < 2; c++)
#pragma unroll
            for (int i = 0; i < 4; i++) acc[c][i] = 0ULL;

        // prologue: stage chunk 0 into buf 0
        {
#pragma unroll
            for (int it = 0; it < 4; it++) {
                int e = it * 512 + tid;
                int bb = e >> 4, kq = e & 15;
                uint32_t dst = hs_u32 + (uint32_t)((bb * 64 + ((kq ^ ((bb >> 2) & 7)) << 2)) * 4);
                cpasync16(dst, g_h + bb * HID + kq * 4);
            }
            asm volatile("cp.async.commit_group;");
        }

#pragma unroll
        for (int ci = 0; ci < 8; ci++) {
            if (ci < 7) {
                int buf = (ci + 1) % 3;
#pragma unroll
                for (int it = 0; it < 4; it++) {
                    int e = it * 512 + tid;
                    int bb = e >> 4, kq = e & 15;
                    uint32_t dst = hs_u32 +
                        (uint32_t)((buf * CHUNKF + bb * 64 + ((kq ^ ((bb >> 2) & 7)) << 2)) * 4);
                    cpasync16(dst, g_h + bb * HID + (ci + 1) * 64 + kq * 4);
                }
                asm volatile("cp.async.commit_group;");
                asm volatile("cp.async.wait_group 1;");
            } else {
                asm volatile("cp.async.wait_group 0;");
            }
            __syncthreads();

            const float* hb  = hs + (ci % 3) * CHUNKF;
            const float* w0r = ws + cA0 * WPITCH;
            const float* w1r = ws + cA1 * WPITCH;
#pragma unroll
            for (int kq8 = 0; kq8 < 8; kq8++) {
                int kq  = kh * 8 + kq8;
                int k4a = ci * 16 + kq;
                ulonglong2 w0 = *(const ulonglong2*)(w0r + ((k4a ^ swc0) << 2));
                ulonglong2 w1 = *(const ulonglong2*)(w1r + ((k4a ^ swc1) << 2));
#pragma unroll
                for (int i = 0; i < 4; i++) {
                    int b = bq * 4 + i;
                    ulonglong2 hv = *(const ulonglong2*)(hb + b * 64 + ((kq ^ swb) << 2));
                    acc[0][i] = ffma2(hv.x, w0.x, acc[0][i]);
                    acc[0][i] = ffma2(hv.y, w0.y, acc[0][i]);
                    acc[1][i] = ffma2(hv.x, w1.x, acc[1][i]);
                    acc[1][i] = ffma2(hv.y, w1.y, acc[1][i]);
                }
            }
        }

        // combine K halves through smem (red area aliases buf 0)
        u64* red = (u64*)hs;
        if (kh == 1) {
#pragma unroll
            for (int c = 0; c < 2; c++)
#pragma unroll
                for (int i = 0; i < 4; i++) red[r * 8 + c * 4 + i] = acc[c][i];
        }
        __syncthreads();
        if (kh == 0) {
            float p0[4] = {pre0.x, pre0.y, pre0.z, pre0.w};
            float p1[4] = {pre1.x, pre1.y, pre1.z, pre1.w};
#pragma unroll
            for (int i = 0; i < 4; i++) {
                int b = bq * 4 + i;
                u64 s0 = fadd2(acc[0][i], red[r * 8 + i]);
                u64 s1 = fadd2(acc[1][i], red[r * 8 + 4 + i]);
                float lo, hi, v0, v1;
                unpack2(s0, lo, hi); v0 = lo + hi + p0[i];
                unpack2(s1, lo, hi); v1 = lo + hi + p1[i];
                *(float2*)&g_cosv[b * NCOL + col0] = make_float2(__cosf(v0), __cosf(v1));
            }
        }
        rnd++; gridbar(rnd);

        // ---------------- phase B: scan + activations + cell (batch = j) ---
        {
            int gate = tid >> 7;
            int lg   = tid & 127;
            int lane = tid & 31;
            int wg   = (tid >> 5) & 3;
            const float* src = g_cosv + j * NCOL + gate * HID + lg * 4;
            float4 a = __ldcg((const float4*)src);
            float xv[4] = {a.x, a.y, a.z, a.w};
            float p = xv[0] * xv[1] * xv[2] * xv[3];
            float inc = p;
#pragma unroll
            for (int off = 1; off < 32; off <<= 1) {
                float y = __shfl_up_sync(0xffffffffu, inc, off);
                if (lane >= off) inc *= y;
            }
            float excl = __shfl_up_sync(0xffffffffu, inc, 1);
            if (lane == 0) excl = 1.f;
            if (lane == 31) wtot[gate * 4 + wg] = inc;
            __syncthreads();
#pragma unroll
            for (int w = 0; w < 3; w++)
                if (wg > w) excl *= wtot[gate * 4 + w];
            float run = excl;
#pragma unroll
            for (int i = 0; i < 4; i++) {
                run *= xv[i];
                float act = (gate == 2) ? tanhf(run)
                                        : 1.f / (1.f + __expf(-run));
                gsm[gate * HID + lg * 4 + i] = act;
            }
        }
        __syncthreads();
        {
            int n = tid;
            float f  = gsm[n];
            float ii = gsm[HID + n];
            float gg = gsm[2 * HID + n];
            float o  = gsm[3 * HID + n];
            float cc = f * csm[n] + ii * gg;
            csm[n] = cc;
            float h = o * tanhf(cc);
            g_h[j * HID + n] = h;
            out[(size_t)t * BH + j * HID + n] = h;
            if (wstate && t == T_STEPS - 1) {
                out[(size_t)TBH + j * HID + n] = h;
                out[(size_t)TBH + BH + j * HID + n] = cc;
            }
        }
        rnd++; gridbar(rnd);
    }
}

#define RECUR_SMEM ((8256 + 24576 + 2048 + 512 + 16) * 4)

extern "C" void kernel_launch(void* const* d_in, const int* in_sizes, int n_in,
                              void* d_out, int out_size) {
    const float* x   = (const float*)d_in[0];
    const float* Wf  = (const float*)d_in[1];
    const float* bf  = (const float*)d_in[2];
    const float* thf = (const float*)d_in[3];
    const float* Wi  = (const float*)d_in[4];
    const float* bi  = (const float*)d_in[5];
    const float* thi = (const float*)d_in[6];
    const float* Wu  = (const float*)d_in[7];
    const float* bu  = (const float*)d_in[8];
    const float* thu = (const float*)d_in[9];
    const float* Wo  = (const float*)d_in[10];
    const float* bo  = (const float*)d_in[11];
    const float* tho = (const float*)d_in[12];
    float* out = (float*)d_out;
    int wstate = (out_size >= TBH + 2 * BH) ? 1 : 0;

    pre_gemm<<<dim3(16, 256), 256>>>(x, Wf, bf, thf, Wi, bi, thi,
                                     Wu, bu, thu, Wo, bo, tho);

    cudaFuncSetAttribute(qlstm_recur,
                         cudaFuncAttributeMaxDynamicSharedMemorySize, RECUR_SMEM);
    qlstm_recur<<<NB, 512, RECUR_SMEM>>>(Wf, Wi, Wu, Wo, out, wstate);
}